// round 15
// baseline (speedup 1.0000x reference)
#include <cuda_runtime.h>
#include <cuda_bf16.h>
#include <math.h>
#include <stdint.h>

#define QSCALE 0.07216878364870322f  // 1/sqrt(192)

// Scratch (device globals; no allocation allowed)
__device__ float    g_q  [64ull*1024*64];
__device__ float    g_k  [64ull*1024*64];
__device__ float    g_v  [64ull*1024*64];
__device__ float    g_pk [16ull*1024*64];
__device__ float    g_pq [16ull*1024*64];
__device__ uint32_t g_bias2[64ull*1024*1024]; // [bh][i][j] packed {bf16 c2p | bf16 p2c}, in-band only
__device__ float    g_ce0[64ull*1024];        // c2p[i][0]
__device__ float    g_ce1[64ull*1024];        // c2p[i][1023]
__device__ float    g_e0 [64ull*1024];        // p2c[j][0]
__device__ float    g_e1 [64ull*1024];        // p2c[j][1023]
// Pre-rounded (tf32-RNA) copies of GEMM inputs, enabling cp.async pipelines
__device__ float    g_xr [4ull*1024*1024];    // X
__device__ float    g_wr [3ull*1024*1024];    // W_in
__device__ float    g_relr[1ull*1024*1024];   // rel
__device__ float    g_wp0[1ull*1024*1024];    // W_pos
__device__ float    g_wp1[1ull*1024*1024];    // W_posq

__device__ __forceinline__ float f2tf(float x) {
    uint32_t u; asm("cvt.rna.tf32.f32 %0, %1;" : "=r"(u) : "f"(x));
    return __uint_as_float(u);
}
__device__ __forceinline__ float unpack_sum(uint32_t u) {
    __nv_bfloat162 b = *reinterpret_cast<__nv_bfloat162*>(&u);
    float2 f = __bfloat1622float2(b);
    return f.x + f.y;
}
__device__ __forceinline__ void mma8(float* c, const uint32_t* a, const uint32_t* b) {
    asm volatile("mma.sync.aligned.m16n8k8.row.col.f32.tf32.tf32.f32 "
        "{%0,%1,%2,%3}, {%4,%5,%6,%7}, {%8,%9}, {%0,%1,%2,%3};"
        : "+f"(c[0]), "+f"(c[1]), "+f"(c[2]), "+f"(c[3])
        : "r"(a[0]), "r"(a[1]), "r"(a[2]), "r"(a[3]), "r"(b[0]), "r"(b[1]));
}

#define CP_ASYNC16(dst_u32, src_ptr) \
    asm volatile("cp.async.cg.shared.global [%0], [%1], 16;" :: "r"(dst_u32), "l"(src_ptr))
#define CP_COMMIT() asm volatile("cp.async.commit_group;")
#define CP_WAIT1()  asm volatile("cp.async.wait_group 1;")

// ---------------------------------------------------------------------------
// K0: pre-round inputs to tf32 (RNA) so GEMMs can stream them via cp.async.
// ---------------------------------------------------------------------------
__global__ void k_round4(const float4* __restrict__ src, float4* __restrict__ dst, int n4) {
    int i = blockIdx.x * 256 + threadIdx.x;
    const int stride = gridDim.x * 256;
    for (; i < n4; i += stride) {
        float4 v = src[i];
        v.x = f2tf(v.x); v.y = f2tf(v.y); v.z = f2tf(v.z); v.w = f2tf(v.w);
        dst[i] = v;
    }
}

// ---------------------------------------------------------------------------
// K1: qkv = Xr @ Wr (4096x3072x1024), cp.async double-buffered.
// Dynamic smem: sA[2][128][36] + sB[2][32][136] = 71680 B.
// ---------------------------------------------------------------------------
__global__ __launch_bounds__(256, 2) void k_qkv2(
        const float* __restrict__ qb, const float* __restrict__ vb) {
    extern __shared__ float smem[];
    float* sAb[2] = { smem,        smem + 4608 };          // [128][36] each
    float* sBb[2] = { smem + 9216, smem + 9216 + 4352 };   // [32][136] each
    const float* __restrict__ X = g_xr;
    const float* __restrict__ W = g_wr;

    const int t = threadIdx.x;
    const int m0 = blockIdx.y * 128, n0 = blockIdx.x * 128;
    const int wid = t >> 5, lane = t & 31;
    const int wm = wid & 3, wn = wid >> 2;
    const int grp = lane >> 2, tig = lane & 3;
    float acc[2][8][4] = {};
    const int ar = t >> 3, ac = (t & 7) * 4;
    const int br = t >> 5, bc = (t & 31) * 4;

    auto issue_tile = [&](int kb, int buf) {
        #pragma unroll
        for (int p = 0; p < 4; p++) {
            const uint32_t dA = (uint32_t)__cvta_generic_to_shared(&sAb[buf][(ar + 32*p)*36 + ac]);
            CP_ASYNC16(dA, &X[(size_t)(m0 + ar + 32*p)*1024 + kb + ac]);
        }
        #pragma unroll
        for (int p = 0; p < 4; p++) {
            const uint32_t dB = (uint32_t)__cvta_generic_to_shared(&sBb[buf][(br + 8*p)*136 + bc]);
            CP_ASYNC16(dB, &W[(size_t)(kb + br + 8*p)*3072 + n0 + bc]);
        }
    };

    issue_tile(0, 0);
    CP_COMMIT();

    for (int it = 0; it < 32; it++) {
        if (it < 31) issue_tile((it + 1) * 32, (it + 1) & 1);
        CP_COMMIT();
        CP_WAIT1();
        __syncthreads();
        const float* sA = sAb[it & 1];
        const float* sB = sBb[it & 1];
        #pragma unroll
        for (int ks = 0; ks < 32; ks += 8) {
            uint32_t af[2][4];
            #pragma unroll
            for (int mt = 0; mt < 2; mt++) {
                const int r = wm*32 + mt*16;
                af[mt][0] = __float_as_uint(sA[(r+grp  )*36 + ks+tig  ]);
                af[mt][1] = __float_as_uint(sA[(r+grp+8)*36 + ks+tig  ]);
                af[mt][2] = __float_as_uint(sA[(r+grp  )*36 + ks+tig+4]);
                af[mt][3] = __float_as_uint(sA[(r+grp+8)*36 + ks+tig+4]);
            }
            #pragma unroll
            for (int nt = 0; nt < 8; nt++) {
                uint32_t bf[2];
                const int cn = wn*64 + nt*8 + grp;
                bf[0] = __float_as_uint(sB[(ks+tig  )*136 + cn]);
                bf[1] = __float_as_uint(sB[(ks+tig+4)*136 + cn]);
                mma8(acc[0][nt], af[0], bf);
                mma8(acc[1][nt], af[1], bf);
            }
        }
        __syncthreads();
    }
    #pragma unroll
    for (int mt = 0; mt < 2; mt++)
        #pragma unroll
        for (int nt = 0; nt < 8; nt++)
            #pragma unroll
            for (int e = 0; e < 4; e++) {
                const int m = m0 + wm*32 + mt*16 + grp + (e >> 1) * 8;
                const int n = n0 + wn*64 + nt*8 + tig*2 + (e & 1);
                const int bb = m >> 10, l = m & 1023;
                const int h = n / 192, c = n - h * 192;
                const float val = acc[mt][nt][e];
                const size_t base = (((size_t)bb*16 + h)*1024 + l)*64;
                if (c < 64)       g_q[base + c]        = f2tf((val + qb[h*64 + c]) * QSCALE);
                else if (c < 128) g_k[base + (c-64)]   = f2tf(val);
                else              g_v[base + (c-128)]  = f2tf(val + vb[h*64 + (c-128)]);
            }
}

// ---------------------------------------------------------------------------
// K2: pos projections, cp.async double-buffered.
// z=0: pk = relr@Wp0 ; z=1: pq = (relr@Wp1 + b)*QSCALE
// ---------------------------------------------------------------------------
__global__ __launch_bounds__(256, 2) void k_pos2(const float* __restrict__ bias) {
    extern __shared__ float smem[];
    float* sAb[2] = { smem,        smem + 4608 };
    float* sBb[2] = { smem + 9216, smem + 9216 + 4352 };
    const int mode = blockIdx.z;
    const float* __restrict__ R = g_relr;
    const float* __restrict__ W = mode ? g_wp1 : g_wp0;

    const int t = threadIdx.x;
    const int m0 = blockIdx.y * 128, n0 = blockIdx.x * 128;
    const int wid = t >> 5, lane = t & 31;
    const int wm = wid & 3, wn = wid >> 2;
    const int grp = lane >> 2, tig = lane & 3;
    float acc[2][8][4] = {};
    const int ar = t >> 3, ac = (t & 7) * 4;
    const int br = t >> 5, bc = (t & 31) * 4;

    auto issue_tile = [&](int kb, int buf) {
        #pragma unroll
        for (int p = 0; p < 4; p++) {
            const uint32_t dA = (uint32_t)__cvta_generic_to_shared(&sAb[buf][(ar + 32*p)*36 + ac]);
            CP_ASYNC16(dA, &R[(size_t)(m0 + ar + 32*p)*1024 + kb + ac]);
        }
        #pragma unroll
        for (int p = 0; p < 4; p++) {
            const uint32_t dB = (uint32_t)__cvta_generic_to_shared(&sBb[buf][(br + 8*p)*136 + bc]);
            CP_ASYNC16(dB, &W[(size_t)(kb + br + 8*p)*1024 + n0 + bc]);
        }
    };

    issue_tile(0, 0);
    CP_COMMIT();

    for (int it = 0; it < 32; it++) {
        if (it < 31) issue_tile((it + 1) * 32, (it + 1) & 1);
        CP_COMMIT();
        CP_WAIT1();
        __syncthreads();
        const float* sA = sAb[it & 1];
        const float* sB = sBb[it & 1];
        #pragma unroll
        for (int ks = 0; ks < 32; ks += 8) {
            uint32_t af[2][4];
            #pragma unroll
            for (int mt = 0; mt < 2; mt++) {
                const int r = wm*32 + mt*16;
                af[mt][0] = __float_as_uint(sA[(r+grp  )*36 + ks+tig  ]);
                af[mt][1] = __float_as_uint(sA[(r+grp+8)*36 + ks+tig  ]);
                af[mt][2] = __float_as_uint(sA[(r+grp  )*36 + ks+tig+4]);
                af[mt][3] = __float_as_uint(sA[(r+grp+8)*36 + ks+tig+4]);
            }
            #pragma unroll
            for (int nt = 0; nt < 8; nt++) {
                uint32_t bf[2];
                const int cn = wn*64 + nt*8 + grp;
                bf[0] = __float_as_uint(sB[(ks+tig  )*136 + cn]);
                bf[1] = __float_as_uint(sB[(ks+tig+4)*136 + cn]);
                mma8(acc[0][nt], af[0], bf);
                mma8(acc[1][nt], af[1], bf);
            }
        }
        __syncthreads();
    }
    #pragma unroll
    for (int mt = 0; mt < 2; mt++)
        #pragma unroll
        for (int nt = 0; nt < 8; nt++)
            #pragma unroll
            for (int e = 0; e < 4; e++) {
                const int s = m0 + wm*32 + mt*16 + grp + (e >> 1) * 8;
                const int n = n0 + wn*64 + nt*8 + tig*2 + (e & 1);
                const int h = n >> 6, d = n & 63;
                const float val = acc[mt][nt][e];
                if (mode) g_pq[((size_t)h*1024 + s)*64 + d] = f2tf((val + bias[n]) * QSCALE);
                else      g_pk[((size_t)h*1024 + s)*64 + d] = f2tf(val);
            }
}

// ---------------------------------------------------------------------------
// K3: c2p[i,s] = q_i . pk_s; store bf16 into LOW half of g_bias2[i][j=i-s+512]
// (in-band only); edge columns s=0 / s=1023 -> g_ce0/g_ce1 (fp32).
// ---------------------------------------------------------------------------
__global__ __launch_bounds__(256, 2) void k_c2pg() {
    __shared__ float sA [128][36];
    __shared__ float sBn[128][36];
    const int bh = blockIdx.z, h = bh & 15;
    const float* A  = g_q  + (size_t)bh * 1024 * 64;
    const float* Bn = g_pk + (size_t)h  * 1024 * 64;
    __nv_bfloat16* outB = reinterpret_cast<__nv_bfloat16*>(g_bias2 + ((size_t)bh << 20));
    const int t = threadIdx.x;
    const int m0 = blockIdx.y * 128, n0 = blockIdx.x * 128;
    const int wid = t >> 5, lane = t & 31;
    const int wm = wid & 3, wn = wid >> 2;
    const int grp = lane >> 2, tig = lane & 3;
    float acc[2][8][4] = {};
    const int ar = t >> 3, ac = (t & 7) * 4;

    for (int kb = 0; kb < 64; kb += 32) {
        #pragma unroll
        for (int p = 0; p < 4; p++) {
            *(float4*)&sA [ar + p*32][ac] = *(const float4*)&A [(size_t)(m0 + ar + p*32)*64 + kb + ac];
            *(float4*)&sBn[ar + p*32][ac] = *(const float4*)&Bn[(size_t)(n0 + ar + p*32)*64 + kb + ac];
        }
        __syncthreads();
        #pragma unroll
        for (int ks = 0; ks < 32; ks += 8) {
            uint32_t af[2][4];
            #pragma unroll
            for (int mt = 0; mt < 2; mt++) {
                const int r = wm*32 + mt*16;
                af[mt][0] = __float_as_uint(sA[r+grp  ][ks+tig  ]);
                af[mt][1] = __float_as_uint(sA[r+grp+8][ks+tig  ]);
                af[mt][2] = __float_as_uint(sA[r+grp  ][ks+tig+4]);
                af[mt][3] = __float_as_uint(sA[r+grp+8][ks+tig+4]);
            }
            #pragma unroll
            for (int nt = 0; nt < 8; nt++) {
                uint32_t bf[2];
                const int cn = wn*64 + nt*8 + grp;
                bf[0] = __float_as_uint(sBn[cn][ks+tig  ]);
                bf[1] = __float_as_uint(sBn[cn][ks+tig+4]);
                mma8(acc[0][nt], af[0], bf);
                mma8(acc[1][nt], af[1], bf);
            }
        }
        __syncthreads();
    }
    #pragma unroll
    for (int mt = 0; mt < 2; mt++)
        #pragma unroll
        for (int nt = 0; nt < 8; nt++)
            #pragma unroll
            for (int e = 0; e < 4; e++) {
                const int i = m0 + wm*32 + mt*16 + grp + (e >> 1) * 8;
                const int s = n0 + wn*64 + nt*8 + tig*2 + (e & 1);
                const float val = acc[mt][nt][e];
                const int j = i - s + 512;
                if ((unsigned)j <= 1023u)
                    outB[2*((size_t)i * 1024 + j)] = __float2bfloat16(val);
                if (s == 0)    g_ce0[(size_t)bh*1024 + i] = val;
                if (s == 1023) g_ce1[(size_t)bh*1024 + i] = val;
            }
}

// ---------------------------------------------------------------------------
// K4: E[j,s] = k_j . pq_s; transpose-scatter bf16 into HIGH half of
// g_bias2[i=j+s-512][j] (disjoint bytes from K3 -> no RMW). Edges -> g_e0/g_e1.
// ---------------------------------------------------------------------------
__global__ __launch_bounds__(256, 2) void k_p2cT() {
    __shared__ float sraw[9472];
    float (*sA)[36]  = (float(*)[36])sraw;
    float (*sBn)[36] = (float(*)[36])(sraw + 4608);
    float (*sm)[68]  = (float(*)[68])sraw;

    const int bh = blockIdx.z, h = bh & 15;
    const float* A  = g_k  + (size_t)bh * 1024 * 64;
    const float* Bn = g_pq + (size_t)h  * 1024 * 64;
    const int t = threadIdx.x;
    const int m0 = blockIdx.y * 128, n0 = blockIdx.x * 128;   // m=j, n=s
    const int wid = t >> 5, lane = t & 31;
    const int wm = wid & 3, wn = wid >> 2;
    const int grp = lane >> 2, tig = lane & 3;
    float acc[2][8][4] = {};
    const int ar = t >> 3, ac = (t & 7) * 4;

    for (int kb = 0; kb < 64; kb += 32) {
        #pragma unroll
        for (int p = 0; p < 4; p++) {
            *(float4*)&sA [ar + p*32][ac] = *(const float4*)&A [(size_t)(m0 + ar + p*32)*64 + kb + ac];
            *(float4*)&sBn[ar + p*32][ac] = *(const float4*)&Bn[(size_t)(n0 + ar + p*32)*64 + kb + ac];
        }
        __syncthreads();
        #pragma unroll
        for (int ks = 0; ks < 32; ks += 8) {
            uint32_t af[2][4];
            #pragma unroll
            for (int mt = 0; mt < 2; mt++) {
                const int r = wm*32 + mt*16;
                af[mt][0] = __float_as_uint(sA[r+grp  ][ks+tig  ]);
                af[mt][1] = __float_as_uint(sA[r+grp+8][ks+tig  ]);
                af[mt][2] = __float_as_uint(sA[r+grp  ][ks+tig+4]);
                af[mt][3] = __float_as_uint(sA[r+grp+8][ks+tig+4]);
            }
            #pragma unroll
            for (int nt = 0; nt < 8; nt++) {
                uint32_t bf[2];
                const int cn = wn*64 + nt*8 + grp;
                bf[0] = __float_as_uint(sBn[cn][ks+tig  ]);
                bf[1] = __float_as_uint(sBn[cn][ks+tig+4]);
                mma8(acc[0][nt], af[0], bf);
                mma8(acc[1][nt], af[1], bf);
            }
        }
        __syncthreads();
    }

    __nv_bfloat16* PT = reinterpret_cast<__nv_bfloat16*>(g_bias2 + ((size_t)bh << 20));
    #pragma unroll
    for (int half = 0; half < 2; half++) {
        if (wn == half) {
            #pragma unroll
            for (int mt = 0; mt < 2; mt++)
                #pragma unroll
                for (int nt = 0; nt < 8; nt++)
                    #pragma unroll
                    for (int e = 0; e < 4; e++) {
                        const int row = wm*32 + mt*16 + grp + (e >> 1) * 8;  // local j
                        const int col = nt*8 + tig*2 + (e & 1);              // local s
                        sm[row][col] = acc[mt][nt][e];
                    }
        }
        __syncthreads();
        const int sbase = n0 + half*64;
        if (sbase == 0)
            for (int r = t; r < 128; r += 256) g_e0[(size_t)bh*1024 + m0 + r] = sm[r][0];
        if (sbase == 960)
            for (int r = t; r < 128; r += 256) g_e1[(size_t)bh*1024 + m0 + r] = sm[r][63];
        for (int rr = wid; rr < 191; rr += 8) {
            const int i = m0 + sbase - 512 + rr;
            if ((unsigned)i > 1023u) continue;
            const int jl = max(m0, i + 512 - (sbase + 63));
            const int jh = min(m0 + 127, i + 512 - sbase);
            for (int j = jl + lane; j <= jh; j += 32) {
                const int s = i - j + 512;
                PT[2*((size_t)i * 1024 + j) + 1] = __float2bfloat16(sm[j - m0][s - sbase]);
            }
        }
        __syncthreads();
    }
}

// ---------------------------------------------------------------------------
// K5: fused attention, no-max softmax, corner-aware, PIPELINED (unchanged).
// Dynamic smem: sK[2][64*68] sV[2][64*72] sP[128*68] = 106496 B.
// ---------------------------------------------------------------------------
__global__ __launch_bounds__(256, 2) void k_flash7(float* __restrict__ out) {
    extern __shared__ float smem[];
    float* sKb[2] = { smem,        smem + 4352 };
    float* sVb[2] = { smem + 8704, smem + 13312 };
    float* sP     = smem + 17920;

    const int bh = blockIdx.y, bb = bh >> 4, h = bh & 15;
    const int i0 = blockIdx.x * 128;
    const int t = threadIdx.x, wid = t >> 5, lane = t & 31;
    const int grp = lane >> 2, tig = lane & 3;
    const int rloc = wid*16 + grp;
    const int rA = i0 + rloc;

    const float*    __restrict__ Q  = g_q + (size_t)bh * 1024 * 64;
    const float*    __restrict__ K  = g_k + (size_t)bh * 1024 * 64;
    const float*    __restrict__ V  = g_v + (size_t)bh * 1024 * 64;
    const uint32_t* __restrict__ BP = g_bias2 + ((size_t)bh << 20);
    const float*    __restrict__ E0 = g_e0 + (size_t)bh * 1024;
    const float*    __restrict__ E1 = g_e1 + (size_t)bh * 1024;

    const float ceA0 = g_ce0[(size_t)bh*1024 + rA],     ceA1 = g_ce1[(size_t)bh*1024 + rA];
    const float ceB0 = g_ce0[(size_t)bh*1024 + rA + 8], ceB1 = g_ce1[(size_t)bh*1024 + rA + 8];

    uint32_t qf[8][4];
    #pragma unroll
    for (int kc = 0; kc < 8; kc++) {
        qf[kc][0] = __float_as_uint(Q[(size_t)(rA  )*64 + kc*8 + tig    ]);
        qf[kc][1] = __float_as_uint(Q[(size_t)(rA+8)*64 + kc*8 + tig    ]);
        qf[kc][2] = __float_as_uint(Q[(size_t)(rA  )*64 + kc*8 + tig + 4]);
        qf[kc][3] = __float_as_uint(Q[(size_t)(rA+8)*64 + kc*8 + tig + 4]);
    }

    const int lrow = t >> 2, lcb = (t & 3) * 16;
    auto issue_tile = [&](int jt, int buf) {
        const uint32_t dK = (uint32_t)__cvta_generic_to_shared(&sKb[buf][lrow*68 + lcb]);
        const uint32_t dV = (uint32_t)__cvta_generic_to_shared(&sVb[buf][lrow*72 + lcb]);
        const float* gK = &K[(size_t)(jt*64 + lrow)*64 + lcb];
        const float* gV = &V[(size_t)(jt*64 + lrow)*64 + lcb];
        #pragma unroll
        for (int p = 0; p < 4; p++) {
            CP_ASYNC16(dK + p*16, gK + p*4);
            CP_ASYNC16(dV + p*16, gV + p*4);
        }
    };

    issue_tile(0, 0);
    CP_COMMIT();

    float O[8][4] = {};
    float lA = 0.f, lB = 0.f;

    for (int it = 0; it < 16; it++) {
        const int j0 = it * 64;
        if (it < 15) issue_tile(it + 1, (it + 1) & 1);
        CP_COMMIT();
        CP_WAIT1();
        __syncthreads();

        const float* cK = sKb[it & 1];
        const float* cV = sVb[it & 1];

        const int srbase = i0 - j0 + 512;
        const bool inA   = (srbase >= 63 && srbase <= 896);
        const bool allLo = (srbase <= -128);
        const bool allHi = (srbase >= 1087);
        const bool needPlane = !(allLo || allHi);
        const bool loSide = (srbase < 512);
        const float cA = loSide ? ceA0 : ceA1;
        const float cB = loSide ? ceB0 : ceB1;
        const float* __restrict__ Eg = loSide ? E0 : E1;

        #pragma unroll
        for (int half = 0; half < 2; half++) {
            uint2 bA[4], bB[4];
            if (needPlane) {
                #pragma unroll
                for (int q = 0; q < 4; q++) {
                    const int c = half*32 + q*8 + tig*2;
                    bA[q] = *(const uint2*)&BP[(size_t)rA*1024 + j0 + c];
                    bB[q] = *(const uint2*)&BP[(size_t)(rA+8)*1024 + j0 + c];
                }
            }
            float p[4][4] = {};
            #pragma unroll
            for (int kc = 0; kc < 8; kc++) {
                #pragma unroll
                for (int q = 0; q < 4; q++) {
                    uint32_t bf[2];
                    const int c = (half*32 + q*8 + grp) * 68 + kc*8 + tig;
                    bf[0] = __float_as_uint(cK[c]);
                    bf[1] = __float_as_uint(cK[c + 4]);
                    mma8(p[q], qf[kc], bf);
                }
            }
            #pragma unroll
            for (int q = 0; q < 4; q++) {
                const int c  = half*32 + q*8 + tig*2;
                const int ra = rloc * 68 + c, rb = (rloc + 8) * 68 + c;
                float b0, b1, b2, b3;
                if (inA) {
                    b0 = unpack_sum(bA[q].x); b1 = unpack_sum(bA[q].y);
                    b2 = unpack_sum(bB[q].x); b3 = unpack_sum(bB[q].y);
                } else if (!needPlane) {
                    const float2 e2 = *(const float2*)&Eg[j0 + c];
                    b0 = cA + e2.x; b1 = cA + e2.y;
                    b2 = cB + e2.x; b3 = cB + e2.y;
                } else {
                    #pragma unroll
                    for (int e = 0; e < 2; e++) {
                        const int jj = j0 + c + e;
                        const int srA2 = rA - jj + 512;
                        const uint32_t wA = e ? bA[q].y : bA[q].x;
                        const uint32_t wB = e ? bB[q].y : bB[q].x;
                        float vA = ((unsigned)srA2 <= 1023u) ? unpack_sum(wA) : cA + Eg[jj];
                        float vB = ((unsigned)(srA2 + 8) <= 1023u) ? unpack_sum(wB) : cB + Eg[jj];
                        if (e) { b1 = vA; b3 = vB; } else { b0 = vA; b2 = vB; }
                    }
                }
                float v0 = __expf(p[q][0] + b0);
                float v1 = __expf(p[q][1] + b1);
                float v2 = __expf(p[q][2] + b2);
                float v3 = __expf(p[q][3] + b3);
                lA += v0 + v1; lB += v2 + v3;
                sP[ra    ] = f2tf(v0);
                sP[ra + 1] = f2tf(v1);
                sP[rb    ] = f2tf(v2);
                sP[rb + 1] = f2tf(v3);
            }
        }
        __syncthreads();

        #pragma unroll
        for (int kc = 0; kc < 8; kc++) {
            uint32_t af[4];
            const int r = rloc * 68 + kc*8 + tig;
            af[0] = __float_as_uint(sP[r]);
            af[1] = __float_as_uint(sP[r + 8*68]);
            af[2] = __float_as_uint(sP[r + 4]);
            af[3] = __float_as_uint(sP[r + 8*68 + 4]);
            #pragma unroll
            for (int nt = 0; nt < 8; nt++) {
                uint32_t bf[2];
                const int c = (kc*8 + tig) * 72 + nt*8 + grp;
                bf[0] = __float_as_uint(cV[c]);
                bf[1] = __float_as_uint(cV[c + 4*72]);
                mma8(O[nt], af, bf);
            }
        }
        __syncthreads();
    }

    lA += __shfl_xor_sync(0xffffffffu, lA, 1);
    lA += __shfl_xor_sync(0xffffffffu, lA, 2);
    lB += __shfl_xor_sync(0xffffffffu, lB, 1);
    lB += __shfl_xor_sync(0xffffffffu, lB, 2);
    const float invA = 1.f / lA, invB = 1.f / lB;
    #pragma unroll
    for (int nt = 0; nt < 8; nt++) {
        const int d = nt*8 + tig*2;
        float2 oA = make_float2(O[nt][0] * invA, O[nt][1] * invA);
        float2 oB = make_float2(O[nt][2] * invB, O[nt][3] * invB);
        *(float2*)&out[((size_t)bb*1024 + rA    )*1024 + h*64 + d] = oA;
        *(float2*)&out[((size_t)bb*1024 + rA + 8)*1024 + h*64 + d] = oB;
    }
}

// ---------------------------------------------------------------------------
extern "C" void kernel_launch(void* const* d_in, const int* in_sizes, int n_in,
                              void* d_out, int out_size) {
    const float* X      = (const float*)d_in[0];   // (4,1024,1024)
    const float* rel    = (const float*)d_in[2];   // (1024,1024)
    const float* W_in   = (const float*)d_in[3];   // (1024,3072)
    const float* qb     = (const float*)d_in[4];   // (1024,)
    const float* vb     = (const float*)d_in[5];   // (1024,)
    const float* W_pos  = (const float*)d_in[6];   // (1024,1024)
    const float* W_posq = (const float*)d_in[7];   // (1024,1024)
    const float* b_posq = (const float*)d_in[8];   // (1024,)
    float*       out    = (float*)d_out;           // (4,1024,1024)

    static int smem_set = 0;
    if (!smem_set) {
        cudaFuncSetAttribute(k_flash7, cudaFuncAttributeMaxDynamicSharedMemorySize, 106496);
        cudaFuncSetAttribute(k_qkv2,   cudaFuncAttributeMaxDynamicSharedMemorySize, 71680);
        cudaFuncSetAttribute(k_pos2,   cudaFuncAttributeMaxDynamicSharedMemorySize, 71680);
        smem_set = 1;
    }

    // resolve device-global scratch addresses for the pre-round pass
    float *xr, *wr, *relr, *wp0, *wp1;
    cudaGetSymbolAddress((void**)&xr,   g_xr);
    cudaGetSymbolAddress((void**)&wr,   g_wr);
    cudaGetSymbolAddress((void**)&relr, g_relr);
    cudaGetSymbolAddress((void**)&wp0,  g_wp0);
    cudaGetSymbolAddress((void**)&wp1,  g_wp1);

    k_round4<<<1024, 256>>>((const float4*)X,      (float4*)xr,   4*1024*1024/4);
    k_round4<<<1024, 256>>>((const float4*)W_in,   (float4*)wr,   3*1024*1024/4);
    k_round4<<<512,  256>>>((const float4*)rel,    (float4*)relr, 1024*1024/4);
    k_round4<<<512,  256>>>((const float4*)W_pos,  (float4*)wp0,  1024*1024/4);
    k_round4<<<512,  256>>>((const float4*)W_posq, (float4*)wp1,  1024*1024/4);

    k_qkv2  <<<dim3(24, 32),    256, 71680>>>(qb, vb);
    k_pos2  <<<dim3(8, 8, 2),   256, 71680>>>(b_posq);
    k_c2pg  <<<dim3(8, 8, 64),  256>>>();
    k_p2cT  <<<dim3(8, 8, 64),  256>>>();
    k_flash7<<<dim3(8, 64),     256, 106496>>>(out);
}

// round 17
// speedup vs baseline: 1.6408x; 1.6408x over previous
#include <cuda_runtime.h>
#include <cuda_bf16.h>
#include <math.h>
#include <stdint.h>

#define QSCALE 0.07216878364870322f  // 1/sqrt(192)

// Scratch (device globals; no allocation allowed)
__device__ float    g_q  [64ull*1024*64];
__device__ float    g_k  [64ull*1024*64];
__device__ float    g_v  [64ull*1024*64];
__device__ float    g_pk [16ull*1024*64];
__device__ float    g_pq [16ull*1024*64];
__device__ uint32_t g_bias2[64ull*1024*1024]; // [bh][i][j] packed {bf16 c2p | bf16 p2c}, in-band only
__device__ float    g_ce0[64ull*1024];        // c2p[i][0]
__device__ float    g_ce1[64ull*1024];        // c2p[i][1023]
__device__ float    g_e0 [64ull*1024];        // p2c[j][0]
__device__ float    g_e1 [64ull*1024];        // p2c[j][1023]

__device__ __forceinline__ float f2tf(float x) {
    uint32_t u; asm("cvt.rna.tf32.f32 %0, %1;" : "=r"(u) : "f"(x));
    return __uint_as_float(u);
}
__device__ __forceinline__ float unpack_sum(uint32_t u) {
    __nv_bfloat162 b = *reinterpret_cast<__nv_bfloat162*>(&u);
    float2 f = __bfloat1622float2(b);
    return f.x + f.y;
}
__device__ __forceinline__ void mma8(float* c, const uint32_t* a, const uint32_t* b) {
    asm volatile("mma.sync.aligned.m16n8k8.row.col.f32.tf32.tf32.f32 "
        "{%0,%1,%2,%3}, {%4,%5,%6,%7}, {%8,%9}, {%0,%1,%2,%3};"
        : "+f"(c[0]), "+f"(c[1]), "+f"(c[2]), "+f"(c[3])
        : "r"(a[0]), "r"(a[1]), "r"(a[2]), "r"(a[3]), "r"(b[0]), "r"(b[1]));
}

#define CP_ASYNC16(dst_u32, src_ptr) \
    asm volatile("cp.async.cg.shared.global [%0], [%1], 16;" :: "r"(dst_u32), "l"(src_ptr))
#define CP_COMMIT() asm volatile("cp.async.commit_group;")
#define CP_WAIT1()  asm volatile("cp.async.wait_group 1;")

// ---------------------------------------------------------------------------
// K1: qkv = X @ W_in (4096x3072x1024), scatter into g_q/g_k/g_v (tf32-rounded)
// (R14-verified form)
// ---------------------------------------------------------------------------
__global__ __launch_bounds__(256, 2) void k_qkv(
        const float* __restrict__ X, const float* __restrict__ W,
        const float* __restrict__ qb, const float* __restrict__ vb) {
    __shared__ float sA[128][36];
    __shared__ float sB[32][136];
    const int t = threadIdx.x;
    const int m0 = blockIdx.y * 128, n0 = blockIdx.x * 128;
    const int wid = t >> 5, lane = t & 31;
    const int wm = wid & 3, wn = wid >> 2;
    const int grp = lane >> 2, tig = lane & 3;
    float acc[2][8][4] = {};
    const int ar = t >> 3, ac = (t & 7) * 4;
    const int br = t >> 5, bc = (t & 31) * 4;

    for (int kb = 0; kb < 1024; kb += 32) {
        #pragma unroll
        for (int p = 0; p < 4; p++) {
            float4 v4 = *(const float4*)&X[(size_t)(m0 + ar + p*32)*1024 + kb + ac];
            v4.x = f2tf(v4.x); v4.y = f2tf(v4.y); v4.z = f2tf(v4.z); v4.w = f2tf(v4.w);
            *(float4*)&sA[ar + p*32][ac] = v4;
        }
        #pragma unroll
        for (int p = 0; p < 4; p++) {
            float4 v4 = *(const float4*)&W[(size_t)(kb + br + p*8)*3072 + n0 + bc];
            v4.x = f2tf(v4.x); v4.y = f2tf(v4.y); v4.z = f2tf(v4.z); v4.w = f2tf(v4.w);
            *(float4*)&sB[br + p*8][bc] = v4;
        }
        __syncthreads();
        #pragma unroll
        for (int ks = 0; ks < 32; ks += 8) {
            uint32_t af[2][4];
            #pragma unroll
            for (int mt = 0; mt < 2; mt++) {
                const int r = wm*32 + mt*16;
                af[mt][0] = __float_as_uint(sA[r+grp  ][ks+tig  ]);
                af[mt][1] = __float_as_uint(sA[r+grp+8][ks+tig  ]);
                af[mt][2] = __float_as_uint(sA[r+grp  ][ks+tig+4]);
                af[mt][3] = __float_as_uint(sA[r+grp+8][ks+tig+4]);
            }
            #pragma unroll
            for (int nt = 0; nt < 8; nt++) {
                uint32_t bf[2];
                const int cn = wn*64 + nt*8 + grp;
                bf[0] = __float_as_uint(sB[ks+tig  ][cn]);
                bf[1] = __float_as_uint(sB[ks+tig+4][cn]);
                mma8(acc[0][nt], af[0], bf);
                mma8(acc[1][nt], af[1], bf);
            }
        }
        __syncthreads();
    }
    #pragma unroll
    for (int mt = 0; mt < 2; mt++)
        #pragma unroll
        for (int nt = 0; nt < 8; nt++)
            #pragma unroll
            for (int e = 0; e < 4; e++) {
                const int m = m0 + wm*32 + mt*16 + grp + (e >> 1) * 8;
                const int n = n0 + wn*64 + nt*8 + tig*2 + (e & 1);
                const int bb = m >> 10, l = m & 1023;
                const int h = n / 192, c = n - h * 192;
                const float val = acc[mt][nt][e];
                const size_t base = (((size_t)bb*16 + h)*1024 + l)*64;
                if (c < 64)       g_q[base + c]        = f2tf((val + qb[h*64 + c]) * QSCALE);
                else if (c < 128) g_k[base + (c-64)]   = f2tf(val);
                else              g_v[base + (c-128)]  = f2tf(val + vb[h*64 + (c-128)]);
            }
}

// ---------------------------------------------------------------------------
// K2: pos projections. z=0: pk=rel@W_pos; z=1: pq=(rel@W_posq+b)*QSCALE
// (R14-verified form)
// ---------------------------------------------------------------------------
__global__ __launch_bounds__(256, 2) void k_pos(
        const float* __restrict__ rel, const float* __restrict__ W0,
        const float* __restrict__ W1, const float* __restrict__ bias) {
    __shared__ float sA[128][36];
    __shared__ float sB[32][136];
    const int mode = blockIdx.z;
    const float* Wm = mode ? W1 : W0;
    const int t = threadIdx.x;
    const int m0 = blockIdx.y * 128, n0 = blockIdx.x * 128;
    const int wid = t >> 5, lane = t & 31;
    const int wm = wid & 3, wn = wid >> 2;
    const int grp = lane >> 2, tig = lane & 3;
    float acc[2][8][4] = {};
    const int ar = t >> 3, ac = (t & 7) * 4;
    const int br = t >> 5, bc = (t & 31) * 4;

    for (int kb = 0; kb < 1024; kb += 32) {
        #pragma unroll
        for (int p = 0; p < 4; p++) {
            float4 v4 = *(const float4*)&rel[(size_t)(m0 + ar + p*32)*1024 + kb + ac];
            v4.x = f2tf(v4.x); v4.y = f2tf(v4.y); v4.z = f2tf(v4.z); v4.w = f2tf(v4.w);
            *(float4*)&sA[ar + p*32][ac] = v4;
        }
        #pragma unroll
        for (int p = 0; p < 4; p++) {
            float4 v4 = *(const float4*)&Wm[(size_t)(kb + br + p*8)*1024 + n0 + bc];
            v4.x = f2tf(v4.x); v4.y = f2tf(v4.y); v4.z = f2tf(v4.z); v4.w = f2tf(v4.w);
            *(float4*)&sB[br + p*8][bc] = v4;
        }
        __syncthreads();
        #pragma unroll
        for (int ks = 0; ks < 32; ks += 8) {
            uint32_t af[2][4];
            #pragma unroll
            for (int mt = 0; mt < 2; mt++) {
                const int r = wm*32 + mt*16;
                af[mt][0] = __float_as_uint(sA[r+grp  ][ks+tig  ]);
                af[mt][1] = __float_as_uint(sA[r+grp+8][ks+tig  ]);
                af[mt][2] = __float_as_uint(sA[r+grp  ][ks+tig+4]);
                af[mt][3] = __float_as_uint(sA[r+grp+8][ks+tig+4]);
            }
            #pragma unroll
            for (int nt = 0; nt < 8; nt++) {
                uint32_t bf[2];
                const int cn = wn*64 + nt*8 + grp;
                bf[0] = __float_as_uint(sB[ks+tig  ][cn]);
                bf[1] = __float_as_uint(sB[ks+tig+4][cn]);
                mma8(acc[0][nt], af[0], bf);
                mma8(acc[1][nt], af[1], bf);
            }
        }
        __syncthreads();
    }
    #pragma unroll
    for (int mt = 0; mt < 2; mt++)
        #pragma unroll
        for (int nt = 0; nt < 8; nt++)
            #pragma unroll
            for (int e = 0; e < 4; e++) {
                const int s = m0 + wm*32 + mt*16 + grp + (e >> 1) * 8;
                const int n = n0 + wn*64 + nt*8 + tig*2 + (e & 1);
                const int h = n >> 6, d = n & 63;
                const float val = acc[mt][nt][e];
                if (mode) g_pq[((size_t)h*1024 + s)*64 + d] = f2tf((val + bias[n]) * QSCALE);
                else      g_pk[((size_t)h*1024 + s)*64 + d] = f2tf(val);
            }
}

// ---------------------------------------------------------------------------
// K3: c2p[i,s] = q_i . pk_s; store bf16 into LOW half of g_bias2[i][j=i-s+512]
// (in-band only); edge columns s=0 / s=1023 -> g_ce0/g_ce1 (fp32).
// ---------------------------------------------------------------------------
__global__ __launch_bounds__(256, 2) void k_c2pg() {
    __shared__ float sA [128][36];
    __shared__ float sBn[128][36];
    const int bh = blockIdx.z, h = bh & 15;
    const float* A  = g_q  + (size_t)bh * 1024 * 64;
    const float* Bn = g_pk + (size_t)h  * 1024 * 64;
    __nv_bfloat16* outB = reinterpret_cast<__nv_bfloat16*>(g_bias2 + ((size_t)bh << 20));
    const int t = threadIdx.x;
    const int m0 = blockIdx.y * 128, n0 = blockIdx.x * 128;
    const int wid = t >> 5, lane = t & 31;
    const int wm = wid & 3, wn = wid >> 2;
    const int grp = lane >> 2, tig = lane & 3;
    float acc[2][8][4] = {};
    const int ar = t >> 3, ac = (t & 7) * 4;

    for (int kb = 0; kb < 64; kb += 32) {
        #pragma unroll
        for (int p = 0; p < 4; p++) {
            *(float4*)&sA [ar + p*32][ac] = *(const float4*)&A [(size_t)(m0 + ar + p*32)*64 + kb + ac];
            *(float4*)&sBn[ar + p*32][ac] = *(const float4*)&Bn[(size_t)(n0 + ar + p*32)*64 + kb + ac];
        }
        __syncthreads();
        #pragma unroll
        for (int ks = 0; ks < 32; ks += 8) {
            uint32_t af[2][4];
            #pragma unroll
            for (int mt = 0; mt < 2; mt++) {
                const int r = wm*32 + mt*16;
                af[mt][0] = __float_as_uint(sA[r+grp  ][ks+tig  ]);
                af[mt][1] = __float_as_uint(sA[r+grp+8][ks+tig  ]);
                af[mt][2] = __float_as_uint(sA[r+grp  ][ks+tig+4]);
                af[mt][3] = __float_as_uint(sA[r+grp+8][ks+tig+4]);
            }
            #pragma unroll
            for (int nt = 0; nt < 8; nt++) {
                uint32_t bf[2];
                const int cn = wn*64 + nt*8 + grp;
                bf[0] = __float_as_uint(sBn[cn][ks+tig  ]);
                bf[1] = __float_as_uint(sBn[cn][ks+tig+4]);
                mma8(acc[0][nt], af[0], bf);
                mma8(acc[1][nt], af[1], bf);
            }
        }
        __syncthreads();
    }
    #pragma unroll
    for (int mt = 0; mt < 2; mt++)
        #pragma unroll
        for (int nt = 0; nt < 8; nt++)
            #pragma unroll
            for (int e = 0; e < 4; e++) {
                const int i = m0 + wm*32 + mt*16 + grp + (e >> 1) * 8;
                const int s = n0 + wn*64 + nt*8 + tig*2 + (e & 1);
                const float val = acc[mt][nt][e];
                const int j = i - s + 512;
                if ((unsigned)j <= 1023u)
                    outB[2*((size_t)i * 1024 + j)] = __float2bfloat16(val);
                if (s == 0)    g_ce0[(size_t)bh*1024 + i] = val;
                if (s == 1023) g_ce1[(size_t)bh*1024 + i] = val;
            }
}

// ---------------------------------------------------------------------------
// K4: E[j,s] = k_j . pq_s; transpose-scatter bf16 into HIGH half of
// g_bias2[i=j+s-512][j] (disjoint bytes from K3 -> no RMW). Edges -> g_e0/g_e1.
// ---------------------------------------------------------------------------
__global__ __launch_bounds__(256, 2) void k_p2cT() {
    __shared__ float sraw[9472];
    float (*sA)[36]  = (float(*)[36])sraw;
    float (*sBn)[36] = (float(*)[36])(sraw + 4608);
    float (*sm)[68]  = (float(*)[68])sraw;

    const int bh = blockIdx.z, h = bh & 15;
    const float* A  = g_k  + (size_t)bh * 1024 * 64;
    const float* Bn = g_pq + (size_t)h  * 1024 * 64;
    const int t = threadIdx.x;
    const int m0 = blockIdx.y * 128, n0 = blockIdx.x * 128;   // m=j, n=s
    const int wid = t >> 5, lane = t & 31;
    const int wm = wid & 3, wn = wid >> 2;
    const int grp = lane >> 2, tig = lane & 3;
    float acc[2][8][4] = {};
    const int ar = t >> 3, ac = (t & 7) * 4;

    for (int kb = 0; kb < 64; kb += 32) {
        #pragma unroll
        for (int p = 0; p < 4; p++) {
            *(float4*)&sA [ar + p*32][ac] = *(const float4*)&A [(size_t)(m0 + ar + p*32)*64 + kb + ac];
            *(float4*)&sBn[ar + p*32][ac] = *(const float4*)&Bn[(size_t)(n0 + ar + p*32)*64 + kb + ac];
        }
        __syncthreads();
        #pragma unroll
        for (int ks = 0; ks < 32; ks += 8) {
            uint32_t af[2][4];
            #pragma unroll
            for (int mt = 0; mt < 2; mt++) {
                const int r = wm*32 + mt*16;
                af[mt][0] = __float_as_uint(sA[r+grp  ][ks+tig  ]);
                af[mt][1] = __float_as_uint(sA[r+grp+8][ks+tig  ]);
                af[mt][2] = __float_as_uint(sA[r+grp  ][ks+tig+4]);
                af[mt][3] = __float_as_uint(sA[r+grp+8][ks+tig+4]);
            }
            #pragma unroll
            for (int nt = 0; nt < 8; nt++) {
                uint32_t bf[2];
                const int cn = wn*64 + nt*8 + grp;
                bf[0] = __float_as_uint(sBn[cn][ks+tig  ]);
                bf[1] = __float_as_uint(sBn[cn][ks+tig+4]);
                mma8(acc[0][nt], af[0], bf);
                mma8(acc[1][nt], af[1], bf);
            }
        }
        __syncthreads();
    }

    __nv_bfloat16* PT = reinterpret_cast<__nv_bfloat16*>(g_bias2 + ((size_t)bh << 20));
    #pragma unroll
    for (int half = 0; half < 2; half++) {
        if (wn == half) {
            #pragma unroll
            for (int mt = 0; mt < 2; mt++)
                #pragma unroll
                for (int nt = 0; nt < 8; nt++)
                    #pragma unroll
                    for (int e = 0; e < 4; e++) {
                        const int row = wm*32 + mt*16 + grp + (e >> 1) * 8;  // local j
                        const int col = nt*8 + tig*2 + (e & 1);              // local s
                        sm[row][col] = acc[mt][nt][e];
                    }
        }
        __syncthreads();
        const int sbase = n0 + half*64;
        if (sbase == 0)
            for (int r = t; r < 128; r += 256) g_e0[(size_t)bh*1024 + m0 + r] = sm[r][0];
        if (sbase == 960)
            for (int r = t; r < 128; r += 256) g_e1[(size_t)bh*1024 + m0 + r] = sm[r][63];
        for (int rr = wid; rr < 191; rr += 8) {
            const int i = m0 + sbase - 512 + rr;
            if ((unsigned)i > 1023u) continue;
            const int jl = max(m0, i + 512 - (sbase + 63));
            const int jh = min(m0 + 127, i + 512 - sbase);
            for (int j = jl + lane; j <= jh; j += 32) {
                const int s = i - j + 512;
                PT[2*((size_t)i * 1024 + j) + 1] = __float2bfloat16(sm[j - m0][s - sbase]);
            }
        }
        __syncthreads();
    }
}

// ---------------------------------------------------------------------------
// K5: fused attention (R14-verified k_flash7, unchanged).
// Dynamic smem: sK[2][64*68] sV[2][64*72] sP[128*68] = 106496 B.
// ---------------------------------------------------------------------------
__global__ __launch_bounds__(256, 2) void k_flash7(float* __restrict__ out) {
    extern __shared__ float smem[];
    float* sKb[2] = { smem,        smem + 4352 };
    float* sVb[2] = { smem + 8704, smem + 13312 };
    float* sP     = smem + 17920;

    const int bh = blockIdx.y, bb = bh >> 4, h = bh & 15;
    const int i0 = blockIdx.x * 128;
    const int t = threadIdx.x, wid = t >> 5, lane = t & 31;
    const int grp = lane >> 2, tig = lane & 3;
    const int rloc = wid*16 + grp;
    const int rA = i0 + rloc;

    const float*    __restrict__ Q  = g_q + (size_t)bh * 1024 * 64;
    const float*    __restrict__ K  = g_k + (size_t)bh * 1024 * 64;
    const float*    __restrict__ V  = g_v + (size_t)bh * 1024 * 64;
    const uint32_t* __restrict__ BP = g_bias2 + ((size_t)bh << 20);
    const float*    __restrict__ E0 = g_e0 + (size_t)bh * 1024;
    const float*    __restrict__ E1 = g_e1 + (size_t)bh * 1024;

    const float ceA0 = g_ce0[(size_t)bh*1024 + rA],     ceA1 = g_ce1[(size_t)bh*1024 + rA];
    const float ceB0 = g_ce0[(size_t)bh*1024 + rA + 8], ceB1 = g_ce1[(size_t)bh*1024 + rA + 8];

    uint32_t qf[8][4];
    #pragma unroll
    for (int kc = 0; kc < 8; kc++) {
        qf[kc][0] = __float_as_uint(Q[(size_t)(rA  )*64 + kc*8 + tig    ]);
        qf[kc][1] = __float_as_uint(Q[(size_t)(rA+8)*64 + kc*8 + tig    ]);
        qf[kc][2] = __float_as_uint(Q[(size_t)(rA  )*64 + kc*8 + tig + 4]);
        qf[kc][3] = __float_as_uint(Q[(size_t)(rA+8)*64 + kc*8 + tig + 4]);
    }

    const int lrow = t >> 2, lcb = (t & 3) * 16;
    auto issue_tile = [&](int jt, int buf) {
        const uint32_t dK = (uint32_t)__cvta_generic_to_shared(&sKb[buf][lrow*68 + lcb]);
        const uint32_t dV = (uint32_t)__cvta_generic_to_shared(&sVb[buf][lrow*72 + lcb]);
        const float* gK = &K[(size_t)(jt*64 + lrow)*64 + lcb];
        const float* gV = &V[(size_t)(jt*64 + lrow)*64 + lcb];
        #pragma unroll
        for (int p = 0; p < 4; p++) {
            CP_ASYNC16(dK + p*16, gK + p*4);
            CP_ASYNC16(dV + p*16, gV + p*4);
        }
    };

    issue_tile(0, 0);
    CP_COMMIT();

    float O[8][4] = {};
    float lA = 0.f, lB = 0.f;

    for (int it = 0; it < 16; it++) {
        const int j0 = it * 64;
        if (it < 15) issue_tile(it + 1, (it + 1) & 1);
        CP_COMMIT();
        CP_WAIT1();
        __syncthreads();

        const float* cK = sKb[it & 1];
        const float* cV = sVb[it & 1];

        const int srbase = i0 - j0 + 512;
        const bool inA   = (srbase >= 63 && srbase <= 896);
        const bool allLo = (srbase <= -128);
        const bool allHi = (srbase >= 1087);
        const bool needPlane = !(allLo || allHi);
        const bool loSide = (srbase < 512);
        const float cA = loSide ? ceA0 : ceA1;
        const float cB = loSide ? ceB0 : ceB1;
        const float* __restrict__ Eg = loSide ? E0 : E1;

        #pragma unroll
        for (int half = 0; half < 2; half++) {
            uint2 bA[4], bB[4];
            if (needPlane) {
                #pragma unroll
                for (int q = 0; q < 4; q++) {
                    const int c = half*32 + q*8 + tig*2;
                    bA[q] = *(const uint2*)&BP[(size_t)rA*1024 + j0 + c];
                    bB[q] = *(const uint2*)&BP[(size_t)(rA+8)*1024 + j0 + c];
                }
            }
            float p[4][4] = {};
            #pragma unroll
            for (int kc = 0; kc < 8; kc++) {
                #pragma unroll
                for (int q = 0; q < 4; q++) {
                    uint32_t bf[2];
                    const int c = (half*32 + q*8 + grp) * 68 + kc*8 + tig;
                    bf[0] = __float_as_uint(cK[c]);
                    bf[1] = __float_as_uint(cK[c + 4]);
                    mma8(p[q], qf[kc], bf);
                }
            }
            #pragma unroll
            for (int q = 0; q < 4; q++) {
                const int c  = half*32 + q*8 + tig*2;
                const int ra = rloc * 68 + c, rb = (rloc + 8) * 68 + c;
                float b0, b1, b2, b3;
                if (inA) {
                    b0 = unpack_sum(bA[q].x); b1 = unpack_sum(bA[q].y);
                    b2 = unpack_sum(bB[q].x); b3 = unpack_sum(bB[q].y);
                } else if (!needPlane) {
                    const float2 e2 = *(const float2*)&Eg[j0 + c];
                    b0 = cA + e2.x; b1 = cA + e2.y;
                    b2 = cB + e2.x; b3 = cB + e2.y;
                } else {
                    #pragma unroll
                    for (int e = 0; e < 2; e++) {
                        const int jj = j0 + c + e;
                        const int srA2 = rA - jj + 512;
                        const uint32_t wA = e ? bA[q].y : bA[q].x;
                        const uint32_t wB = e ? bB[q].y : bB[q].x;
                        float vA = ((unsigned)srA2 <= 1023u) ? unpack_sum(wA) : cA + Eg[jj];
                        float vB = ((unsigned)(srA2 + 8) <= 1023u) ? unpack_sum(wB) : cB + Eg[jj];
                        if (e) { b1 = vA; b3 = vB; } else { b0 = vA; b2 = vB; }
                    }
                }
                float v0 = __expf(p[q][0] + b0);
                float v1 = __expf(p[q][1] + b1);
                float v2 = __expf(p[q][2] + b2);
                float v3 = __expf(p[q][3] + b3);
                lA += v0 + v1; lB += v2 + v3;
                sP[ra    ] = f2tf(v0);
                sP[ra + 1] = f2tf(v1);
                sP[rb    ] = f2tf(v2);
                sP[rb + 1] = f2tf(v3);
            }
        }
        __syncthreads();

        #pragma unroll
        for (int kc = 0; kc < 8; kc++) {
            uint32_t af[4];
            const int r = rloc * 68 + kc*8 + tig;
            af[0] = __float_as_uint(sP[r]);
            af[1] = __float_as_uint(sP[r + 8*68]);
            af[2] = __float_as_uint(sP[r + 4]);
            af[3] = __float_as_uint(sP[r + 8*68 + 4]);
            #pragma unroll
            for (int nt = 0; nt < 8; nt++) {
                uint32_t bf[2];
                const int c = (kc*8 + tig) * 72 + nt*8 + grp;
                bf[0] = __float_as_uint(cV[c]);
                bf[1] = __float_as_uint(cV[c + 4*72]);
                mma8(O[nt], af, bf);
            }
        }
        __syncthreads();
    }

    lA += __shfl_xor_sync(0xffffffffu, lA, 1);
    lA += __shfl_xor_sync(0xffffffffu, lA, 2);
    lB += __shfl_xor_sync(0xffffffffu, lB, 1);
    lB += __shfl_xor_sync(0xffffffffu, lB, 2);
    const float invA = 1.f / lA, invB = 1.f / lB;
    #pragma unroll
    for (int nt = 0; nt < 8; nt++) {
        const int d = nt*8 + tig*2;
        float2 oA = make_float2(O[nt][0] * invA, O[nt][1] * invA);
        float2 oB = make_float2(O[nt][2] * invB, O[nt][3] * invB);
        *(float2*)&out[((size_t)bb*1024 + rA    )*1024 + h*64 + d] = oA;
        *(float2*)&out[((size_t)bb*1024 + rA + 8)*1024 + h*64 + d] = oB;
    }
}

// ---------------------------------------------------------------------------
// Launch: fork-join DAG over two side streams so independent kernels overlap.
//   qkv (s0) || pos (s1)   ->   c2pg (s0) || p2cT (s2)   ->   flash7 (s0)
// Streams/events are host objects created once on the first (eager) call;
// only kernel nodes enter the captured graph.
// ---------------------------------------------------------------------------
extern "C" void kernel_launch(void* const* d_in, const int* in_sizes, int n_in,
                              void* d_out, int out_size) {
    const float* X      = (const float*)d_in[0];   // (4,1024,1024)
    const float* rel    = (const float*)d_in[2];   // (1024,1024)
    const float* W_in   = (const float*)d_in[3];   // (1024,3072)
    const float* qb     = (const float*)d_in[4];   // (1024,)
    const float* vb     = (const float*)d_in[5];   // (1024,)
    const float* W_pos  = (const float*)d_in[6];   // (1024,1024)
    const float* W_posq = (const float*)d_in[7];   // (1024,1024)
    const float* b_posq = (const float*)d_in[8];   // (1024,)
    float*       out    = (float*)d_out;           // (4,1024,1024)

    static int inited = 0;
    static cudaStream_t s1, s2;
    static cudaEvent_t evFork, evPos, evFork2, evP2c;
    if (!inited) {
        cudaFuncSetAttribute(k_flash7, cudaFuncAttributeMaxDynamicSharedMemorySize, 106496);
        cudaStreamCreateWithFlags(&s1, cudaStreamNonBlocking);
        cudaStreamCreateWithFlags(&s2, cudaStreamNonBlocking);
        cudaEventCreateWithFlags(&evFork,  cudaEventDisableTiming);
        cudaEventCreateWithFlags(&evPos,   cudaEventDisableTiming);
        cudaEventCreateWithFlags(&evFork2, cudaEventDisableTiming);
        cudaEventCreateWithFlags(&evP2c,   cudaEventDisableTiming);
        inited = 1;
    }

    // fork: s1 joins the current front of the default stream
    cudaEventRecord(evFork, 0);
    cudaStreamWaitEvent(s1, evFork, 0);

    k_qkv<<<dim3(24, 32), 256, 0, 0 >>>(X, W_in, qb, vb);          // stream 0
    k_pos<<<dim3(8, 8, 2), 256, 0, s1>>>(rel, W_pos, W_posq, b_posq); // stream s1

    // join pos into stream 0, then fork s2 (which now depends on qkv+pos)
    cudaEventRecord(evPos, s1);
    cudaStreamWaitEvent(0, evPos, 0);
    cudaEventRecord(evFork2, 0);
    cudaStreamWaitEvent(s2, evFork2, 0);

    k_c2pg<<<dim3(8, 8, 64), 256, 0, 0 >>>();   // stream 0
    k_p2cT<<<dim3(8, 8, 64), 256, 0, s2>>>();   // stream s2

    // join p2cT back into stream 0
    cudaEventRecord(evP2c, s2);
    cudaStreamWaitEvent(0, evP2c, 0);

    k_flash7<<<dim3(8, 64), 256, 106496, 0>>>(out);
}